// round 11
// baseline (speedup 1.0000x reference)
#include <cuda_runtime.h>
#include <cuda_fp16.h>
#include <cstdint>

#define NB 64
#define NT 2048
#define NM 1024
#define NA 512
#define NQ 1024

#define BM 64             // t-rows per CTA
#define KC 32             // k per B stage (2 MMA k16 steps)
#define NCHUNK (NM / KC)  // 32
#define RSB 20            // B smem row stride (uints): shift-4, conflict-free
#define RSA 516           // A smem row stride (uints): 512 data + 4 pad (shift-4)

#define B_ST (NA * RSB)                  // 10240 uints per B stage
#define A_FULL (BM * RSA)                // 33024 uints (full 64 x 1024 fp16 tile)
#define OFF_A 0
#define OFF_B A_FULL                     // 33024
#define OFF_WQ (OFF_B + 2 * B_ST)        // 53504 (floats from here)
#define OFF_WV (OFF_WQ + NA)
#define OFF_SP (OFF_WV + NA)
#define OFF_ES (OFF_SP + 16 * 64)
#define SMEM_WORDS (OFF_ES + 64)
#define SMEM_SZ (SMEM_WORDS * 4)         // 222464 bytes

#define NSLICE (NT / BM)                 // 32 t-slices per batch

__device__ float g_wq[NB * NA];
__device__ uint32_t g_wm_h[NA * NM / 2];        // Wm as half2 pairs, [a][k/2]
__device__ float g_ctxp[NSLICE * NB * NM];      // context partials [slice][b][m]

__device__ __forceinline__ uint32_t smem_u32(const void* p) {
    uint32_t a;
    asm("{ .reg .u64 t; cvta.to.shared.u64 t, %1; cvt.u32.u64 %0, t; }" : "=r"(a) : "l"(p));
    return a;
}

__device__ __forceinline__ void cpasync16(uint32_t dst, const void* src) {
    asm volatile("cp.async.cg.shared.global [%0], [%1], 16;" :: "r"(dst), "l"(src) : "memory");
}

__device__ __forceinline__ uint32_t pack_h2(float x, float y) {
    __half2 h = __floats2half2_rn(x, y);
    return *(uint32_t*)&h;
}

__device__ __forceinline__ void mma_f16(float& d0, float& d1, float& d2, float& d3,
                                        unsigned a0, unsigned a1, unsigned a2, unsigned a3,
                                        unsigned b0, unsigned b1) {
    asm("mma.sync.aligned.m16n8k16.row.col.f32.f16.f16.f32 "
        "{%0,%1,%2,%3},{%4,%5,%6,%7},{%8,%9},{%0,%1,%2,%3};"
        : "+f"(d0), "+f"(d1), "+f"(d2), "+f"(d3)
        : "r"(a0), "r"(a1), "r"(a2), "r"(a3), "r"(b0), "r"(b1));
}

#define LDMX4(r0, r1, r2, r3, addr) \
    asm volatile("ldmatrix.sync.aligned.m8n8.x4.shared.b16 {%0,%1,%2,%3}, [%4];" \
                 : "=r"(r0), "=r"(r1), "=r"(r2), "=r"(r3) : "r"(addr))

// ---------------------------------------------------------------------------
// Kernel 0 (fused prep): blocks <256: cvt Wm->fp16; blocks >=256: wq GEMM
// wq tiled: block = 128 a-rows x 4 b, query rows staged in smem (Wq L2 32MB)
// ---------------------------------------------------------------------------
__global__ __launch_bounds__(256) void prep_kernel(
    const float* __restrict__ Wm, const float* __restrict__ query,
    const float* __restrict__ Wq)
{
    int bid = blockIdx.x;
    if (bid < 256) {
        int i = bid * 256 + threadIdx.x;
        const float4* s = (const float4*)Wm;
        float4 v0 = s[2 * i], v1 = s[2 * i + 1];
        g_wm_h[4 * i + 0] = pack_h2(v0.x, v0.y);
        g_wm_h[4 * i + 1] = pack_h2(v0.z, v0.w);
        g_wm_h[4 * i + 2] = pack_h2(v1.x, v1.y);
        g_wm_h[4 * i + 3] = pack_h2(v1.z, v1.w);
    } else {
        __shared__ float qs[4 * NQ];
        int id = bid - 256;          // 0..63
        int ag = id & 3, bg = id >> 2;
        for (int i = threadIdx.x; i < 4 * NQ; i += 256)
            qs[i] = query[(bg * 4 + (i >> 10)) * NQ + (i & 1023)];
        __syncthreads();
        if (threadIdx.x < 128) {
            int a = ag * 128 + threadIdx.x;
            const float4* w4 = (const float4*)(Wq + (size_t)a * NQ);
            const float4* q0 = (const float4*)(qs);
            const float4* q1 = (const float4*)(qs + NQ);
            const float4* q2 = (const float4*)(qs + 2 * NQ);
            const float4* q3 = (const float4*)(qs + 3 * NQ);
            float s0 = 0.f, s1 = 0.f, s2 = 0.f, s3 = 0.f;
#pragma unroll 8
            for (int k = 0; k < NQ / 4; k++) {
                float4 w = w4[k];
                float4 a0 = q0[k], a1 = q1[k], a2 = q2[k], a3 = q3[k];
                s0 += w.x * a0.x + w.y * a0.y + w.z * a0.z + w.w * a0.w;
                s1 += w.x * a1.x + w.y * a1.y + w.z * a1.z + w.w * a1.w;
                s2 += w.x * a2.x + w.y * a2.y + w.z * a2.z + w.w * a2.w;
                s3 += w.x * a3.x + w.y * a3.y + w.z * a3.z + w.w * a3.w;
            }
            g_wq[(bg * 4 + 0) * NA + a] = s0;
            g_wq[(bg * 4 + 1) * NA + a] = s1;
            g_wq[(bg * 4 + 2) * NA + a] = s2;
            g_wq[(bg * 4 + 3) * NA + a] = s3;
        }
    }
}

// ---------------------------------------------------------------------------
// Kernel 2: fused fp16 mma.sync GEMM (64 x 512 x 1024) + Wv.tanh(wq+wm)
//           + exp + context partial FROM SMEM (A tile resident all 16 chunks).
// B: KC=32, 2-stage cp.async (issue B(c+1) after sync, wait_group 0 at top).
// A: full 129KB fp16 tile, chunks (KC=64) stored at even iterations.
// ---------------------------------------------------------------------------
__device__ __forceinline__ void issue_B(int c, uint32_t bbuf, int tid) {
    int k2 = c * (KC / 2);                    // uint offset within row
#pragma unroll
    for (int i = 0; i < 4; i++) {             // 512 rows x 4 x 16B
        int e = tid + i * 512;
        int row = e >> 2, c16 = e & 3;
        cpasync16(bbuf + (row * RSB + c16 * 4) * 4,
                  g_wm_h + (size_t)row * (NM / 2) + k2 + c16 * 4);
    }
    asm volatile("cp.async.commit_group;" ::: "memory");
}

__global__ __launch_bounds__(512, 1) void score_kernel(
    const float* __restrict__ mem, const float* __restrict__ Wv,
    float* __restrict__ alpha_un)
{
    extern __shared__ __align__(16) uint32_t smem[];
    uint32_t sbase = smem_u32(smem);
    float* wqs = (float*)(smem + OFF_WQ);
    float* wvs = (float*)(smem + OFF_WV);
    float* spr = (float*)(smem + OFF_SP);
    float* es  = (float*)(smem + OFF_ES);

    int tid = threadIdx.x, wid = tid >> 5, lane = tid & 31;
    int g = lane >> 2, tg = lane & 3;
    int b = blockIdx.y, t0 = blockIdx.x * BM;

    for (int i = tid; i < NA; i += 512) {
        wqs[i] = g_wq[b * NA + i];
        wvs[i] = Wv[i];
    }

    const float* Ag = mem + ((size_t)b * NT + t0) * NM;
    const int arow = tid >> 3, ac = tid & 7;   // A LDG/STS: 64 rows x 8 cols of 8 floats

    // ldmatrix lane-address components
    int q8 = lane >> 3, r8 = lane & 7;
    int aoff = ((q8 & 1) * 8 + r8) * RSA + (q8 >> 1) * 4;
    int boff = ((q8 & 2) * 4 + r8 + wid * 32) * RSB + (q8 & 1) * 4;

    float acc[4][4][4];
#pragma unroll
    for (int mf = 0; mf < 4; mf++)
#pragma unroll
        for (int j = 0; j < 4; j++)
#pragma unroll
            for (int qq = 0; qq < 4; qq++) acc[mf][j][qq] = 0.f;

    // prologue: A chunk 0 (KC=64) in regs; B(0) in flight
    float4 ar0 = *(const float4*)(Ag + (size_t)arow * NM + ac * 8);
    float4 ar1 = *(const float4*)(Ag + (size_t)arow * NM + ac * 8 + 4);
    issue_B(0, sbase + (OFF_B + 0 * B_ST) * 4, tid);

    for (int c = 0; c < NCHUNK; c++) {
        asm volatile("cp.async.wait_group 0;" ::: "memory");   // B(c) landed
        if ((c & 1) == 0) {
            // store A chunk c/2 (k cols [32c, 32c+64)) into persistent slot
            uint4 u;
            u.x = pack_h2(ar0.x, ar0.y);
            u.y = pack_h2(ar0.z, ar0.w);
            u.z = pack_h2(ar1.x, ar1.y);
            u.w = pack_h2(ar1.z, ar1.w);
            *(uint4*)(smem + OFF_A + arow * RSA + (c >> 1) * 32 + ac * 4) = u;
        }
        __syncthreads();   // A visible; B stage (c+1)&1 free (consumed at c-1)
        if (c < NCHUNK - 1)
            issue_B(c + 1, sbase + (OFF_B + ((c + 1) & 1) * B_ST) * 4, tid);
        if ((c & 1) == 0 && c <= NCHUNK - 4) {
            int k0 = ((c >> 1) + 1) * 64;
            ar0 = *(const float4*)(Ag + (size_t)arow * NM + k0 + ac * 8);
            ar1 = *(const float4*)(Ag + (size_t)arow * NM + k0 + ac * 8 + 4);
        }

        uint32_t Abase = sbase + (OFF_A + aoff + c * 16) * 4;
        uint32_t Bbase = sbase + (OFF_B + (c & 1) * B_ST + boff) * 4;
#pragma unroll
        for (int ks = 0; ks < 2; ks++) {
            int ko4 = ks * 8 * 4;
            unsigned af[4][4];
#pragma unroll
            for (int mf = 0; mf < 4; mf++)
                LDMX4(af[mf][0], af[mf][1], af[mf][2], af[mf][3],
                      Abase + ko4 + mf * 16 * RSA * 4);
            unsigned bf[8];
            LDMX4(bf[0], bf[1], bf[2], bf[3], Bbase + ko4);
            LDMX4(bf[4], bf[5], bf[6], bf[7], Bbase + ko4 + 16 * RSB * 4);
#pragma unroll
            for (int j = 0; j < 4; j++) {
                unsigned b0 = bf[j * 2], b1 = bf[j * 2 + 1];
#pragma unroll
                for (int mf = 0; mf < 4; mf++)
                    mma_f16(acc[mf][j][0], acc[mf][j][1], acc[mf][j][2], acc[mf][j][3],
                            af[mf][0], af[mf][1], af[mf][2], af[mf][3], b0, b1);
            }
        }
    }

    // epilogue 1: partial score rows for this warp's 32 cols
    float p0[4], p1[4];
#pragma unroll
    for (int mf = 0; mf < 4; mf++) { p0[mf] = 0.f; p1[mf] = 0.f; }
#pragma unroll
    for (int mf = 0; mf < 4; mf++)
#pragma unroll
        for (int j = 0; j < 4; j++) {
            int a0 = wid * 32 + j * 8 + 2 * tg;
            float w0 = wvs[a0], w1 = wvs[a0 + 1];
            float q0 = wqs[a0], q1 = wqs[a0 + 1];
            p0[mf] += w0 * tanhf(q0 + acc[mf][j][0]) + w1 * tanhf(q1 + acc[mf][j][1]);
            p1[mf] += w0 * tanhf(q0 + acc[mf][j][2]) + w1 * tanhf(q1 + acc[mf][j][3]);
        }
#pragma unroll
    for (int mf = 0; mf < 4; mf++) {
        p0[mf] += __shfl_xor_sync(0xffffffffu, p0[mf], 1);
        p0[mf] += __shfl_xor_sync(0xffffffffu, p0[mf], 2);
        p1[mf] += __shfl_xor_sync(0xffffffffu, p1[mf], 1);
        p1[mf] += __shfl_xor_sync(0xffffffffu, p1[mf], 2);
    }
    if (tg == 0) {
#pragma unroll
        for (int mf = 0; mf < 4; mf++) {
            spr[wid * 64 + mf * 16 + g]     = p0[mf];
            spr[wid * 64 + mf * 16 + 8 + g] = p1[mf];
        }
    }
    __syncthreads();
    if (tid < BM) {
        float s = 0.f;
#pragma unroll
        for (int w = 0; w < 16; w++) s += spr[w * 64 + tid];
        float e = expf(s);                       // no max-subtract: bounded
        alpha_un[b * NT + t0 + tid] = e;
        es[tid] = e;
    }
    __syncthreads();

    // epilogue 2: context partial from the RESIDENT fp16 A tile (no DRAM)
    {
        const uint32_t* Abuf = smem + OFF_A;
        float cx = 0.f, cy = 0.f;                // thread owns m = 2*tid, 2*tid+1
#pragma unroll 8
        for (int t = 0; t < BM; t++) {
            float e = es[t];
            float2 v = __half22float2(*(const __half2*)&Abuf[t * RSA + tid]);
            cx += e * v.x;
            cy += e * v.y;
        }
        float2 out; out.x = cx; out.y = cy;
        *(float2*)(g_ctxp + ((size_t)blockIdx.x * NB + b) * NM + 2 * tid) = out;
    }
}

// ---------------------------------------------------------------------------
// Kernel 3: finalize per batch row: Z, alpha normalize, context reduce
// ---------------------------------------------------------------------------
__global__ __launch_bounds__(256) void finalize_kernel(
    float* __restrict__ alpha, float* __restrict__ ctx)
{
    __shared__ float red[8];
    int b = blockIdx.x, tid = threadIdx.x;
    float* arow = alpha + b * NT;

    float z = 0.f;
#pragma unroll
    for (int i = 0; i < NT / 256; i++) z += arow[tid + 256 * i];
#pragma unroll
    for (int o = 16; o; o >>= 1) z += __shfl_xor_sync(0xffffffffu, z, o);
    if ((tid & 31) == 0) red[tid >> 5] = z;
    __syncthreads();
    z = 0.f;
#pragma unroll
    for (int w = 0; w < 8; w++) z += red[w];
    float inv = 1.f / z;

#pragma unroll
    for (int i = 0; i < NT / 256; i++) arow[tid + 256 * i] *= inv;

    int m = tid * 4;
    float4 s = {0.f, 0.f, 0.f, 0.f};
#pragma unroll 4
    for (int sl = 0; sl < NSLICE; sl++) {
        float4 v = *(const float4*)(g_ctxp + ((size_t)sl * NB + b) * NM + m);
        s.x += v.x; s.y += v.y; s.z += v.z; s.w += v.w;
    }
    s.x *= inv; s.y *= inv; s.z *= inv; s.w *= inv;
    *(float4*)(ctx + b * NM + m) = s;
}

// ---------------------------------------------------------------------------
extern "C" void kernel_launch(void* const* d_in, const int* in_sizes, int n_in,
                              void* d_out, int out_size) {
    const float* query  = (const float*)d_in[0];
    const float* memory = (const float*)d_in[1];
    const float* Wq     = (const float*)d_in[2];
    const float* Wm     = (const float*)d_in[3];
    const float* Wv     = (const float*)d_in[4];
    float* alpha = (float*)d_out;            // [64, 2048]
    float* ctx   = alpha + NB * NT;          // [64, 1024]

    prep_kernel<<<320, 256>>>(Wm, query, Wq);

    cudaFuncSetAttribute(score_kernel, cudaFuncAttributeMaxDynamicSharedMemorySize, SMEM_SZ);
    score_kernel<<<dim3(NSLICE, NB), 512, SMEM_SZ>>>(memory, Wv, alpha);

    finalize_kernel<<<NB, 256>>>(alpha, ctx);
}